// round 15
// baseline (speedup 1.0000x reference)
#include <cuda_runtime.h>
#include <cuda_bf16.h>
#include <cstdint>

#define BATCH 8
#define CIN   32
#define COUT  64
#define HW    (512 * 512)
#define NPIX  (BATCH * HW)
#define TILE  128
#define NT    128

#define XPITCHB 528        // x rows: 132 floats; frag LDS.128 bank-quads (2t+g)%8 distinct
#define WPITCHB 96         // W rows: pair-interleaved; LDS.64 banks distinct per phase

// smem byte offsets
#define XS_OFF  0                      // 32 * 528 = 16896
#define WHI_OFF 16896                  // 64 * 96 = 6144
#define WLO_OFF (WHI_OFF + 6144)
#define BS_OFF  (WLO_OFF + 6144)       // 256
#define SMEM_TOT (BS_OFF + 256)        // 29440 < 48KB static

__device__ __forceinline__ void mma16816(float* c, const uint32_t* a, const uint32_t* b) {
    asm volatile(
        "mma.sync.aligned.m16n8k16.row.col.f32.bf16.bf16.f32 "
        "{%0,%1,%2,%3}, {%4,%5,%6,%7}, {%8,%9}, {%0,%1,%2,%3};"
        : "+f"(c[0]), "+f"(c[1]), "+f"(c[2]), "+f"(c[3])
        : "r"(a[0]), "r"(a[1]), "r"(a[2]), "r"(a[3]), "r"(b[0]), "r"(b[1]));
}

__device__ __forceinline__ uint32_t pack_bf16(__nv_bfloat16 e0, __nv_bfloat16 e1) {
    __nv_bfloat162 v; v.x = e0; v.y = e1;
    return *(uint32_t*)&v;
}
__device__ __forceinline__ uint32_t pack_hi(float a, float b) {
    return pack_bf16(__float2bfloat16(a), __float2bfloat16(b));
}
__device__ __forceinline__ uint32_t pack_lo(float a, float b) {
    __nv_bfloat16 ha = __float2bfloat16(a);
    __nv_bfloat16 hb = __float2bfloat16(b);
    return pack_bf16(__float2bfloat16(a - __bfloat162float(ha)),
                     __float2bfloat16(b - __bfloat162float(hb)));
}

static __device__ __forceinline__ uint32_t smem_u32(const void* p) {
    uint32_t a;
    asm("{ .reg .u64 t; cvta.to.shared.u64 t, %1; cvt.u32.u64 %0, t; }" : "=r"(a) : "l"(p));
    return a;
}

#define CP_ASYNC16(dst, src) \
    asm volatile("cp.async.ca.shared.global [%0], [%1], 16;" :: "r"(dst), "l"(src) : "memory")

__global__ void __launch_bounds__(NT, 4)
spconv_mma_kernel(const float* __restrict__ x,
                  const float* __restrict__ Wg,
                  const float* __restrict__ bias,
                  float* __restrict__ out) {
    __shared__ __align__(16) char smc[SMEM_TOT];
    const uint32_t sb = smem_u32(smc);

    const int tid = threadIdx.x;
    const long long p0 = (long long)blockIdx.x * TILE;
    const int b   = (int)(p0 / HW);
    const int hw0 = (int)(p0 % HW);
    const float* xb = x + (long long)b * CIN * HW + hw0;

    // ---- issue x staging FIRST: 8 coalesced cp.async.128 per thread ----
    #pragma unroll
    for (int it = 0; it < 8; ++it) {
        int i  = tid + it * NT;
        int ch = i >> 5;     // channel
        int q  = i & 31;     // pixel quad
        CP_ASYNC16(sb + XS_OFF + ch * XPITCHB + q * 16, xb + (long long)ch * HW + 4 * q);
    }
    asm volatile("cp.async.commit_group;" ::: "memory");

    // ---- stage W^T hi/lo, pair-interleaved for LDS.64 b-frags (overlaps cp.async) ----
    {
        const int o = tid >> 1;
        const int k = tid & 1;     // k-half: channels 16k..16k+15
        #pragma unroll
        for (int t = 0; t < 4; ++t) {
            int ch0 = 2 * t + 16 * k;      // pair (ch0, ch0+1)
            int ch1 = ch0 + 8;             // pair (ch1, ch1+1)
            float a0 = Wg[ch0 * COUT + o], a1 = Wg[(ch0 + 1) * COUT + o];
            float b0 = Wg[ch1 * COUT + o], b1 = Wg[(ch1 + 1) * COUT + o];
            int off = o * WPITCHB + k * 32 + t * 8;
            *(uint2*)(smc + WHI_OFF + off) = make_uint2(pack_hi(a0, a1), pack_hi(b0, b1));
            *(uint2*)(smc + WLO_OFF + off) = make_uint2(pack_lo(a0, a1), pack_lo(b0, b1));
        }
    }
    if (tid < COUT) ((float*)(smc + BS_OFF))[tid] = bias[tid];

    const int w = tid >> 5;
    const int l = tid & 31;
    const int g = l >> 2;     // groupID
    const int t = l & 3;      // thread-in-group
    const int rowbase = 32 * w;

    // ---- wait x staging, sync (also publishes W smem) ----
    asm volatile("cp.async.wait_group 0;" ::: "memory");
    __syncthreads();

    // ---- x fragments: 8 conflict-free LDS.128; thread owns px rowbase+4g..+3 ----
    // v[c][j]: channel 2t+dd[c], physical pixel rowbase+4g+j
    float v[8][4];
    const char* xsm = smc + XS_OFF;
    #pragma unroll
    for (int c = 0; c < 8; ++c) {
        const int dd = (c & 1) + ((c >> 1) & 1) * 8 + (c >> 2) * 16;  // 0,1,8,9,16,17,24,25
        const int ch = 2 * t + dd;
        float4 f = *(const float4*)(xsm + ch * XPITCHB + (rowbase + 4 * g) * 4);
        v[c][0] = f.x; v[c][1] = f.y; v[c][2] = f.z; v[c][3] = f.w;
    }

    // ---- per-pixel activity (4 consecutive px per thread) via t-quad shfl OR ----
    uint32_t msk[4];
    #pragma unroll
    for (int j = 0; j < 4; ++j) {
        uint32_t m = 0u;
        #pragma unroll
        for (int c = 0; c < 8; ++c) m |= __float_as_uint(v[c][j]) & 0x7FFFFFFFu;
        m |= __shfl_xor_sync(0xFFFFFFFFu, m, 1);
        m |= __shfl_xor_sync(0xFFFFFFFFu, m, 2);
        msk[j] = m;
    }

    // ---- bf16 hi/lo A fragments, row->pixel remap phys(16m+8h+g)=4g+2m+h ----
    // mma tile m, k-half k: a0/a2 use comp 2m (h=0); a1/a3 use comp 2m+1 (h=1)
    uint32_t ah[2][2][4], al[2][2][4];
    #pragma unroll
    for (int m = 0; m < 2; ++m) {
        #pragma unroll
        for (int k = 0; k < 2; ++k) {
            ah[m][k][0] = pack_hi(v[4*k+0][2*m],   v[4*k+1][2*m]);
            ah[m][k][1] = pack_hi(v[4*k+0][2*m+1], v[4*k+1][2*m+1]);
            ah[m][k][2] = pack_hi(v[4*k+2][2*m],   v[4*k+3][2*m]);
            ah[m][k][3] = pack_hi(v[4*k+2][2*m+1], v[4*k+3][2*m+1]);
            al[m][k][0] = pack_lo(v[4*k+0][2*m],   v[4*k+1][2*m]);
            al[m][k][1] = pack_lo(v[4*k+0][2*m+1], v[4*k+1][2*m+1]);
            al[m][k][2] = pack_lo(v[4*k+2][2*m],   v[4*k+3][2*m]);
            al[m][k][3] = pack_lo(v[4*k+2][2*m+1], v[4*k+3][2*m+1]);
        }
    }

    float acc[2][8][4];
    #pragma unroll
    for (int m = 0; m < 2; ++m)
        #pragma unroll
        for (int n = 0; n < 8; ++n)
            #pragma unroll
            for (int r = 0; r < 4; ++r) acc[m][n][r] = 0.0f;

    // ---- mainloop: 3-term bf16 split; b-frags via single LDS.64 each ----
    const char* WH = smc + WHI_OFF;
    const char* WL = smc + WLO_OFF;
    #pragma unroll
    for (int k = 0; k < 2; ++k) {
        #pragma unroll
        for (int nb = 0; nb < 2; ++nb) {
            uint32_t bh[4][2], bl[4][2];
            #pragma unroll
            for (int nn = 0; nn < 4; ++nn) {
                int o = 8 * (4 * nb + nn) + g;
                int off = o * WPITCHB + k * 32 + t * 8;
                uint2 hv = *(const uint2*)(WH + off);
                uint2 lv = *(const uint2*)(WL + off);
                bh[nn][0] = hv.x; bh[nn][1] = hv.y;
                bl[nn][0] = lv.x; bl[nn][1] = lv.y;
            }
            #pragma unroll
            for (int nn = 0; nn < 4; ++nn)
                #pragma unroll
                for (int m = 0; m < 2; ++m)
                    mma16816(acc[m][4 * nb + nn], ah[m][k], bh[nn]);
            #pragma unroll
            for (int nn = 0; nn < 4; ++nn)
                #pragma unroll
                for (int m = 0; m < 2; ++m)
                    mma16816(acc[m][4 * nb + nn], ah[m][k], bl[nn]);
            #pragma unroll
            for (int nn = 0; nn < 4; ++nn)
                #pragma unroll
                for (int m = 0; m < 2; ++m)
                    mma16816(acc[m][4 * nb + nn], al[m][k], bh[nn]);
        }
    }

    // ---- epilogue: thread owns px 4g..4g+3 per output -> full STG.128 ----
    const bool A0 = msk[0] != 0u;
    const bool A1 = msk[1] != 0u;
    const bool A2 = msk[2] != 0u;
    const bool A3 = msk[3] != 0u;

    const float* bs = (const float*)(smc + BS_OFF);
    float* ob = out + (long long)b * COUT * HW + hw0 + rowbase + 4 * g;

    #pragma unroll
    for (int n = 0; n < 8; ++n) {
        int o = 8 * n + 2 * t;
        float2 bv = *(const float2*)(bs + o);

        // output o: px 4g+0..3 = acc[0][n][0], acc[0][n][2], acc[1][n][0], acc[1][n][2]
        float4 r0;
        r0.x = A0 ? acc[0][n][0] + bv.x : 0.0f;
        r0.y = A1 ? acc[0][n][2] + bv.x : 0.0f;
        r0.z = A2 ? acc[1][n][0] + bv.x : 0.0f;
        r0.w = A3 ? acc[1][n][2] + bv.x : 0.0f;
        *(float4*)(ob + (long long)o * HW) = r0;

        // output o+1: acc[m][n][1], acc[m][n][3]
        float4 r1;
        r1.x = A0 ? acc[0][n][1] + bv.y : 0.0f;
        r1.y = A1 ? acc[0][n][3] + bv.y : 0.0f;
        r1.z = A2 ? acc[1][n][1] + bv.y : 0.0f;
        r1.w = A3 ? acc[1][n][3] + bv.y : 0.0f;
        *(float4*)(ob + (long long)(o + 1) * HW) = r1;
    }
}

extern "C" void kernel_launch(void* const* d_in, const int* in_sizes, int n_in,
                              void* d_out, int out_size) {
    const float* x  = (const float*)d_in[0];
    const float* Wg = (const float*)d_in[1];
    const float* bi = (const float*)d_in[2];
    float* out = (float*)d_out;

    const int grid = NPIX / TILE;   // 16384
    spconv_mma_kernel<<<grid, NT>>>(x, Wg, bi, out);
}

// round 16
// speedup vs baseline: 1.4134x; 1.4134x over previous
#include <cuda_runtime.h>
#include <cuda_bf16.h>
#include <cstdint>

#define BATCH 8
#define CIN   32
#define COUT  64
#define HW    (512 * 512)
#define NPIX  (BATCH * HW)
#define TILE  128
#define NT    128

#define XPITCHB 528        // x rows: 132 floats; frag LDS.128 chunk-banks (2t+g)%8 distinct
#define WPITCHB 96         // W rows: pair-interleaved; LDS.64 banks distinct per phase

// smem byte offsets
#define XS_OFF  0                      // 32 * 528 = 16896
#define WHI_OFF 16896                  // 64 * 96 = 6144
#define WLO_OFF (WHI_OFF + 6144)
#define BS_OFF  (WLO_OFF + 6144)       // 256
#define SMEM_TOT (BS_OFF + 256)        // 29440 < 48KB static

__device__ __forceinline__ void mma16816(float* c, const uint32_t* a, const uint32_t* b) {
    asm volatile(
        "mma.sync.aligned.m16n8k16.row.col.f32.bf16.bf16.f32 "
        "{%0,%1,%2,%3}, {%4,%5,%6,%7}, {%8,%9}, {%0,%1,%2,%3};"
        : "+f"(c[0]), "+f"(c[1]), "+f"(c[2]), "+f"(c[3])
        : "r"(a[0]), "r"(a[1]), "r"(a[2]), "r"(a[3]), "r"(b[0]), "r"(b[1]));
}

__device__ __forceinline__ uint32_t pack_bf16(__nv_bfloat16 e0, __nv_bfloat16 e1) {
    __nv_bfloat162 v; v.x = e0; v.y = e1;
    return *(uint32_t*)&v;
}
__device__ __forceinline__ uint32_t pack_hi(float a, float b) {
    return pack_bf16(__float2bfloat16(a), __float2bfloat16(b));
}
__device__ __forceinline__ uint32_t pack_lo(float a, float b) {
    __nv_bfloat16 ha = __float2bfloat16(a);
    __nv_bfloat16 hb = __float2bfloat16(b);
    return pack_bf16(__float2bfloat16(a - __bfloat162float(ha)),
                     __float2bfloat16(b - __bfloat162float(hb)));
}

static __device__ __forceinline__ uint32_t smem_u32(const void* p) {
    uint32_t a;
    asm("{ .reg .u64 t; cvta.to.shared.u64 t, %1; cvt.u32.u64 %0, t; }" : "=r"(a) : "l"(p));
    return a;
}

#define CP_ASYNC16(dst, src) \
    asm volatile("cp.async.ca.shared.global [%0], [%1], 16;" :: "r"(dst), "l"(src) : "memory")

__global__ void __launch_bounds__(NT, 4)
spconv_mma_kernel(const float* __restrict__ x,
                  const float* __restrict__ Wg,
                  const float* __restrict__ bias,
                  float* __restrict__ out) {
    __shared__ __align__(16) char smc[SMEM_TOT];
    const uint32_t sb = smem_u32(smc);

    const int tid = threadIdx.x;
    const long long p0 = (long long)blockIdx.x * TILE;
    const int b   = (int)(p0 / HW);
    const int hw0 = (int)(p0 % HW);
    const float* xb = x + (long long)b * CIN * HW + hw0;

    // ---- issue x staging FIRST: 8 coalesced cp.async.128 per thread ----
    #pragma unroll
    for (int it = 0; it < 8; ++it) {
        int i  = tid + it * NT;
        int ch = i >> 5;     // channel
        int q  = i & 31;     // pixel quad
        CP_ASYNC16(sb + XS_OFF + ch * XPITCHB + q * 16, xb + (long long)ch * HW + 4 * q);
    }
    asm volatile("cp.async.commit_group;" ::: "memory");

    // ---- stage W^T hi/lo, pair-interleaved for LDS.64 b-frags (overlaps cp.async) ----
    {
        const int o = tid >> 1;
        const int k = tid & 1;     // k-half: channels 16k..16k+15
        #pragma unroll
        for (int t = 0; t < 4; ++t) {
            int ch0 = 2 * t + 16 * k;      // pair (ch0, ch0+1)
            int ch1 = ch0 + 8;             // pair (ch1, ch1+1)
            float a0 = Wg[ch0 * COUT + o], a1 = Wg[(ch0 + 1) * COUT + o];
            float b0 = Wg[ch1 * COUT + o], b1 = Wg[(ch1 + 1) * COUT + o];
            int off = o * WPITCHB + k * 32 + t * 8;
            *(uint2*)(smc + WHI_OFF + off) = make_uint2(pack_hi(a0, a1), pack_hi(b0, b1));
            *(uint2*)(smc + WLO_OFF + off) = make_uint2(pack_lo(a0, a1), pack_lo(b0, b1));
        }
    }
    if (tid < COUT) ((float*)(smc + BS_OFF))[tid] = bias[tid];

    const int w = tid >> 5;
    const int l = tid & 31;
    const int g = l >> 2;     // groupID
    const int t = l & 3;      // thread-in-group
    const int rowbase = 32 * w;

    // ---- wait x staging, sync (also publishes W smem) ----
    asm volatile("cp.async.wait_group 0;" ::: "memory");
    __syncthreads();

    float acc[2][8][4];
    #pragma unroll
    for (int m = 0; m < 2; ++m)
        #pragma unroll
        for (int n = 0; n < 8; ++n)
            #pragma unroll
            for (int r = 0; r < 4; ++r) acc[m][n][r] = 0.0f;

    uint32_t msk[4] = {0u, 0u, 0u, 0u};   // physical px rowbase+4g+j

    const char* xsm = smc + XS_OFF;
    const char* WH  = smc + WHI_OFF;
    const char* WL  = smc + WLO_OFF;

    // ---- mainloop: k-major; per k-half: load 4 LDS.128, convert, 24 MMAs ----
    // Row->pixel remap: mma row (16m + 8h + g) -> physical px rowbase + 4g + 2m + h
    #pragma unroll
    for (int k = 0; k < 2; ++k) {
        // x for this k-half: channels 16k + {2t, 2t+1, 2t+8, 2t+9}, px 4g..4g+3
        float4 f[4];
        #pragma unroll
        for (int c = 0; c < 4; ++c) {
            const int ch = 16 * k + 2 * t + (c & 1) + (c >> 1) * 8;
            f[c] = *(const float4*)(xsm + ch * XPITCHB + (rowbase + 4 * g) * 4);
        }

        msk[0] |= (__float_as_uint(f[0].x) | __float_as_uint(f[1].x) |
                   __float_as_uint(f[2].x) | __float_as_uint(f[3].x)) & 0x7FFFFFFFu;
        msk[1] |= (__float_as_uint(f[0].y) | __float_as_uint(f[1].y) |
                   __float_as_uint(f[2].y) | __float_as_uint(f[3].y)) & 0x7FFFFFFFu;
        msk[2] |= (__float_as_uint(f[0].z) | __float_as_uint(f[1].z) |
                   __float_as_uint(f[2].z) | __float_as_uint(f[3].z)) & 0x7FFFFFFFu;
        msk[3] |= (__float_as_uint(f[0].w) | __float_as_uint(f[1].w) |
                   __float_as_uint(f[2].w) | __float_as_uint(f[3].w)) & 0x7FFFFFFFu;

        // A fragments for both m-tiles of this k-half
        // a0 = (row g,   k 2t..): comps 2m of f0,f1 ; a1 = (row g+8): comps 2m+1
        // a2 = (row g,   k 2t+8): comps 2m of f2,f3 ; a3 = (row g+8): comps 2m+1
        uint32_t ah[2][4], al[2][4];
        {
            const float* fp = (const float*)f;   // f[c] components: fp[4c + j]
            #pragma unroll
            for (int m = 0; m < 2; ++m) {
                ah[m][0] = pack_hi(fp[0 + 2*m],  fp[4 + 2*m]);
                ah[m][1] = pack_hi(fp[0 + 2*m+1], fp[4 + 2*m+1]);
                ah[m][2] = pack_hi(fp[8 + 2*m],  fp[12 + 2*m]);
                ah[m][3] = pack_hi(fp[8 + 2*m+1], fp[12 + 2*m+1]);
                al[m][0] = pack_lo(fp[0 + 2*m],  fp[4 + 2*m]);
                al[m][1] = pack_lo(fp[0 + 2*m+1], fp[4 + 2*m+1]);
                al[m][2] = pack_lo(fp[8 + 2*m],  fp[12 + 2*m]);
                al[m][3] = pack_lo(fp[8 + 2*m+1], fp[12 + 2*m+1]);
            }
        }

        #pragma unroll
        for (int nb = 0; nb < 2; ++nb) {
            uint32_t bh[4][2], bl[4][2];
            #pragma unroll
            for (int nn = 0; nn < 4; ++nn) {
                int o = 8 * (4 * nb + nn) + g;
                int off = o * WPITCHB + k * 32 + t * 8;
                uint2 hv = *(const uint2*)(WH + off);
                uint2 lv = *(const uint2*)(WL + off);
                bh[nn][0] = hv.x; bh[nn][1] = hv.y;
                bl[nn][0] = lv.x; bl[nn][1] = lv.y;
            }
            #pragma unroll
            for (int nn = 0; nn < 4; ++nn)
                #pragma unroll
                for (int m = 0; m < 2; ++m)
                    mma16816(acc[m][4 * nb + nn], ah[m], bh[nn]);
            #pragma unroll
            for (int nn = 0; nn < 4; ++nn)
                #pragma unroll
                for (int m = 0; m < 2; ++m)
                    mma16816(acc[m][4 * nb + nn], ah[m], bl[nn]);
            #pragma unroll
            for (int nn = 0; nn < 4; ++nn)
                #pragma unroll
                for (int m = 0; m < 2; ++m)
                    mma16816(acc[m][4 * nb + nn], al[m], bh[nn]);
        }
    }

    // combine masks across t-quad (each thread's 4 px are its own, but channels split over t)
    #pragma unroll
    for (int j = 0; j < 4; ++j) {
        msk[j] |= __shfl_xor_sync(0xFFFFFFFFu, msk[j], 1);
        msk[j] |= __shfl_xor_sync(0xFFFFFFFFu, msk[j], 2);
    }
    const bool A0 = msk[0] != 0u;
    const bool A1 = msk[1] != 0u;
    const bool A2 = msk[2] != 0u;
    const bool A3 = msk[3] != 0u;

    // ---- epilogue: thread owns px 4g..4g+3 per output -> full STG.128 ----
    const float* bs = (const float*)(smc + BS_OFF);
    float* ob = out + (long long)b * COUT * HW + hw0 + rowbase + 4 * g;

    #pragma unroll
    for (int n = 0; n < 8; ++n) {
        int o = 8 * n + 2 * t;
        float2 bv = *(const float2*)(bs + o);

        // output o: px 4g+0..3 = (m=0,r0),(m=0,r2),(m=1,r0),(m=1,r2)
        float4 r0;
        r0.x = A0 ? acc[0][n][0] + bv.x : 0.0f;
        r0.y = A1 ? acc[0][n][2] + bv.x : 0.0f;
        r0.z = A2 ? acc[1][n][0] + bv.x : 0.0f;
        r0.w = A3 ? acc[1][n][2] + bv.x : 0.0f;
        *(float4*)(ob + (long long)o * HW) = r0;

        // output o+1: (m,r1),(m,r3)
        float4 r1;
        r1.x = A0 ? acc[0][n][1] + bv.y : 0.0f;
        r1.y = A1 ? acc[0][n][3] + bv.y : 0.0f;
        r1.z = A2 ? acc[1][n][1] + bv.y : 0.0f;
        r1.w = A3 ? acc[1][n][3] + bv.y : 0.0f;
        *(float4*)(ob + (long long)(o + 1) * HW) = r1;
    }
}

extern "C" void kernel_launch(void* const* d_in, const int* in_sizes, int n_in,
                              void* d_out, int out_size) {
    const float* x  = (const float*)d_in[0];
    const float* Wg = (const float*)d_in[1];
    const float* bi = (const float*)d_in[2];
    float* out = (float*)d_out;

    const int grid = NPIX / TILE;   // 16384
    spconv_mma_kernel<<<grid, NT>>>(x, Wg, bi, out);
}

// round 17
// speedup vs baseline: 1.4273x; 1.0098x over previous
#include <cuda_runtime.h>
#include <cuda_bf16.h>
#include <cstdint>

#define BATCH 8
#define CIN   32
#define COUT  64
#define HW    (512 * 512)
#define NPIX  (BATCH * HW)
#define TILE  256            // two 128-px subtiles, double-buffered
#define SUB   128
#define NT    128

#define XPITCHB 528        // x rows: 132 floats; frag LDS.128 chunk-banks distinct
#define WPITCHB 96         // W rows: pair-interleaved; LDS.64 banks distinct per phase

// smem byte offsets
#define XS0_OFF 0                      // 32 * 528 = 16896
#define XS1_OFF 16896                  // 16896
#define WHI_OFF 33792                  // 64 * 96 = 6144
#define WLO_OFF (WHI_OFF + 6144)
#define BS_OFF  (WLO_OFF + 6144)       // 256
#define SMEM_TOT (BS_OFF + 256)        // 46336 < 48KB static

__device__ __forceinline__ void mma16816(float* c, const uint32_t* a, const uint32_t* b) {
    asm volatile(
        "mma.sync.aligned.m16n8k16.row.col.f32.bf16.bf16.f32 "
        "{%0,%1,%2,%3}, {%4,%5,%6,%7}, {%8,%9}, {%0,%1,%2,%3};"
        : "+f"(c[0]), "+f"(c[1]), "+f"(c[2]), "+f"(c[3])
        : "r"(a[0]), "r"(a[1]), "r"(a[2]), "r"(a[3]), "r"(b[0]), "r"(b[1]));
}

__device__ __forceinline__ uint32_t pack_bf16(__nv_bfloat16 e0, __nv_bfloat16 e1) {
    __nv_bfloat162 v; v.x = e0; v.y = e1;
    return *(uint32_t*)&v;
}
__device__ __forceinline__ uint32_t pack_hi(float a, float b) {
    return pack_bf16(__float2bfloat16(a), __float2bfloat16(b));
}
__device__ __forceinline__ uint32_t pack_lo(float a, float b) {
    __nv_bfloat16 ha = __float2bfloat16(a);
    __nv_bfloat16 hb = __float2bfloat16(b);
    return pack_bf16(__float2bfloat16(a - __bfloat162float(ha)),
                     __float2bfloat16(b - __bfloat162float(hb)));
}

static __device__ __forceinline__ uint32_t smem_u32(const void* p) {
    uint32_t a;
    asm("{ .reg .u64 t; cvta.to.shared.u64 t, %1; cvt.u32.u64 %0, t; }" : "=r"(a) : "l"(p));
    return a;
}

#define CP_ASYNC16(dst, src) \
    asm volatile("cp.async.ca.shared.global [%0], [%1], 16;" :: "r"(dst), "l"(src) : "memory")

__global__ void __launch_bounds__(NT, 4)
spconv_mma_kernel(const float* __restrict__ x,
                  const float* __restrict__ Wg,
                  const float* __restrict__ bias,
                  float* __restrict__ out) {
    __shared__ __align__(16) char smc[SMEM_TOT];
    const uint32_t sb = smem_u32(smc);

    const int tid = threadIdx.x;
    const long long p0 = (long long)blockIdx.x * TILE;
    const int b   = (int)(p0 / HW);
    const int hw0 = (int)(p0 % HW);
    const float* xb = x + (long long)b * CIN * HW + hw0;

    // ---- prefetch BOTH subtiles: 8 cp.async.128 per thread per subtile ----
    #pragma unroll
    for (int it = 0; it < 8; ++it) {
        int i  = tid + it * NT;
        int ch = i >> 5;
        int q  = i & 31;
        CP_ASYNC16(sb + XS0_OFF + ch * XPITCHB + q * 16, xb + (long long)ch * HW + 4 * q);
    }
    asm volatile("cp.async.commit_group;" ::: "memory");
    #pragma unroll
    for (int it = 0; it < 8; ++it) {
        int i  = tid + it * NT;
        int ch = i >> 5;
        int q  = i & 31;
        CP_ASYNC16(sb + XS1_OFF + ch * XPITCHB + q * 16,
                   xb + (long long)ch * HW + SUB + 4 * q);
    }
    asm volatile("cp.async.commit_group;" ::: "memory");

    // ---- stage W^T hi/lo once (overlaps both prefetches) ----
    {
        const int o = tid >> 1;
        const int k = tid & 1;
        #pragma unroll
        for (int t = 0; t < 4; ++t) {
            int ch0 = 2 * t + 16 * k;
            int ch1 = ch0 + 8;
            float a0 = Wg[ch0 * COUT + o], a1 = Wg[(ch0 + 1) * COUT + o];
            float b0 = Wg[ch1 * COUT + o], b1 = Wg[(ch1 + 1) * COUT + o];
            int off = o * WPITCHB + k * 32 + t * 8;
            *(uint2*)(smc + WHI_OFF + off) = make_uint2(pack_hi(a0, a1), pack_hi(b0, b1));
            *(uint2*)(smc + WLO_OFF + off) = make_uint2(pack_lo(a0, a1), pack_lo(b0, b1));
        }
    }
    if (tid < COUT) ((float*)(smc + BS_OFF))[tid] = bias[tid];

    const int w = tid >> 5;
    const int l = tid & 31;
    const int g = l >> 2;
    const int t = l & 3;
    const int rowbase = 32 * w;

    const char* WH = smc + WHI_OFF;
    const char* WL = smc + WLO_OFF;
    const float* bs = (const float*)(smc + BS_OFF);

    // ---- two subtiles, pipelined ----
    #pragma unroll
    for (int s = 0; s < 2; ++s) {
        if (s == 0) asm volatile("cp.async.wait_group 1;" ::: "memory");
        else        asm volatile("cp.async.wait_group 0;" ::: "memory");
        __syncthreads();

        const char* xsm = smc + (s == 0 ? XS0_OFF : XS1_OFF);

        float acc[2][8][4];
        #pragma unroll
        for (int m = 0; m < 2; ++m)
            #pragma unroll
            for (int n = 0; n < 8; ++n)
                #pragma unroll
                for (int r = 0; r < 4; ++r) acc[m][n][r] = 0.0f;

        uint32_t msk[4] = {0u, 0u, 0u, 0u};

        // mainloop: k-major; per k-half: 4 LDS.128, convert, 24 MMAs
        // Row->pixel remap: mma row (16m + 8h + g) -> physical px rowbase + 4g + 2m + h
        #pragma unroll
        for (int k = 0; k < 2; ++k) {
            float4 f[4];
            #pragma unroll
            for (int c = 0; c < 4; ++c) {
                const int ch = 16 * k + 2 * t + (c & 1) + (c >> 1) * 8;
                f[c] = *(const float4*)(xsm + ch * XPITCHB + (rowbase + 4 * g) * 4);
            }

            msk[0] |= (__float_as_uint(f[0].x) | __float_as_uint(f[1].x) |
                       __float_as_uint(f[2].x) | __float_as_uint(f[3].x)) & 0x7FFFFFFFu;
            msk[1] |= (__float_as_uint(f[0].y) | __float_as_uint(f[1].y) |
                       __float_as_uint(f[2].y) | __float_as_uint(f[3].y)) & 0x7FFFFFFFu;
            msk[2] |= (__float_as_uint(f[0].z) | __float_as_uint(f[1].z) |
                       __float_as_uint(f[2].z) | __float_as_uint(f[3].z)) & 0x7FFFFFFFu;
            msk[3] |= (__float_as_uint(f[0].w) | __float_as_uint(f[1].w) |
                       __float_as_uint(f[2].w) | __float_as_uint(f[3].w)) & 0x7FFFFFFFu;

            uint32_t ah[2][4], al[2][4];
            {
                const float* fp = (const float*)f;
                #pragma unroll
                for (int m = 0; m < 2; ++m) {
                    ah[m][0] = pack_hi(fp[0 + 2*m],   fp[4 + 2*m]);
                    ah[m][1] = pack_hi(fp[0 + 2*m+1], fp[4 + 2*m+1]);
                    ah[m][2] = pack_hi(fp[8 + 2*m],   fp[12 + 2*m]);
                    ah[m][3] = pack_hi(fp[8 + 2*m+1], fp[12 + 2*m+1]);
                    al[m][0] = pack_lo(fp[0 + 2*m],   fp[4 + 2*m]);
                    al[m][1] = pack_lo(fp[0 + 2*m+1], fp[4 + 2*m+1]);
                    al[m][2] = pack_lo(fp[8 + 2*m],   fp[12 + 2*m]);
                    al[m][3] = pack_lo(fp[8 + 2*m+1], fp[12 + 2*m+1]);
                }
            }

            #pragma unroll
            for (int nb = 0; nb < 2; ++nb) {
                uint32_t bh[4][2], bl[4][2];
                #pragma unroll
                for (int nn = 0; nn < 4; ++nn) {
                    int o = 8 * (4 * nb + nn) + g;
                    int off = o * WPITCHB + k * 32 + t * 8;
                    uint2 hv = *(const uint2*)(WH + off);
                    uint2 lv = *(const uint2*)(WL + off);
                    bh[nn][0] = hv.x; bh[nn][1] = hv.y;
                    bl[nn][0] = lv.x; bl[nn][1] = lv.y;
                }
                #pragma unroll
                for (int nn = 0; nn < 4; ++nn)
                    #pragma unroll
                    for (int m = 0; m < 2; ++m)
                        mma16816(acc[m][4 * nb + nn], ah[m], bh[nn]);
                #pragma unroll
                for (int nn = 0; nn < 4; ++nn)
                    #pragma unroll
                    for (int m = 0; m < 2; ++m)
                        mma16816(acc[m][4 * nb + nn], ah[m], bl[nn]);
                #pragma unroll
                for (int nn = 0; nn < 4; ++nn)
                    #pragma unroll
                    for (int m = 0; m < 2; ++m)
                        mma16816(acc[m][4 * nb + nn], al[m], bh[nn]);
            }
        }

        #pragma unroll
        for (int j = 0; j < 4; ++j) {
            msk[j] |= __shfl_xor_sync(0xFFFFFFFFu, msk[j], 1);
            msk[j] |= __shfl_xor_sync(0xFFFFFFFFu, msk[j], 2);
        }
        const bool A0 = msk[0] != 0u;
        const bool A1 = msk[1] != 0u;
        const bool A2 = msk[2] != 0u;
        const bool A3 = msk[3] != 0u;

        // epilogue: thread owns px 4g..4g+3 per output -> full STG.128
        float* ob = out + (long long)b * COUT * HW + hw0 + s * SUB + rowbase + 4 * g;
        #pragma unroll
        for (int n = 0; n < 8; ++n) {
            int o = 8 * n + 2 * t;
            float2 bv = *(const float2*)(bs + o);

            float4 r0;
            r0.x = A0 ? acc[0][n][0] + bv.x : 0.0f;
            r0.y = A1 ? acc[0][n][2] + bv.x : 0.0f;
            r0.z = A2 ? acc[1][n][0] + bv.x : 0.0f;
            r0.w = A3 ? acc[1][n][2] + bv.x : 0.0f;
            *(float4*)(ob + (long long)o * HW) = r0;

            float4 r1;
            r1.x = A0 ? acc[0][n][1] + bv.y : 0.0f;
            r1.y = A1 ? acc[0][n][3] + bv.y : 0.0f;
            r1.z = A2 ? acc[1][n][1] + bv.y : 0.0f;
            r1.w = A3 ? acc[1][n][3] + bv.y : 0.0f;
            *(float4*)(ob + (long long)(o + 1) * HW) = r1;
        }
    }
}

extern "C" void kernel_launch(void* const* d_in, const int* in_sizes, int n_in,
                              void* d_out, int out_size) {
    const float* x  = (const float*)d_in[0];
    const float* Wg = (const float*)d_in[1];
    const float* bi = (const float*)d_in[2];
    float* out = (float*)d_out;

    const int grid = NPIX / TILE;   // 8192
    spconv_mma_kernel<<<grid, NT>>>(x, Wg, bi, out);
}